// round 1
// baseline (speedup 1.0000x reference)
#include <cuda_runtime.h>
#include <cstddef>

// FastNGramLM advance:
//   for each hypothesis state: chase backoff chain (<=3 hops to START),
//   overlay sparse arcs (first-found-by-depth wins, acc = accumulated backoff
//   weight BEFORE leaving that state), then dense start-state fallback with
//   total accumulated backoff weight.
//
// Output layout: d_out[0 .. B*V)       = scores (float32)
//                d_out[B*V .. 2*B*V)   = next_states (exact float32, < 2^24)

#define TPB 256
#define VMAX 1024

__global__ __launch_bounds__(TPB)
void ngram_advance_kernel(const float*  __restrict__ arcs_weights,
                          const float*  __restrict__ backoff_weights,
                          const int*    __restrict__ ilabels,
                          const int*    __restrict__ to_states,
                          const int*    __restrict__ backoff_to,
                          const int*    __restrict__ state_start,
                          const int*    __restrict__ state_end,
                          const int*    __restrict__ states,
                          float*        __restrict__ out_scores,
                          float*        __restrict__ out_next,
                          int V)
{
    __shared__ float         s_score[VMAX];
    __shared__ int           s_next[VMAX];
    __shared__ unsigned char s_found[VMAX];
    __shared__ float         s_acc;

    const int b   = blockIdx.x;
    const int tid = threadIdx.x;

    // clear found flags
    for (int i = tid; i < V; i += TPB) s_found[i] = 0;
    __syncthreads();

    // Warp 0 walks the backoff chain. cur/acc are uniform across the warp
    // (every lane loads the same scalars -> broadcast), so branches are uniform.
    if (tid < 32) {
        int   cur = states[b];
        float acc = 0.0f;
        #pragma unroll
        for (int d = 0; d < 3; ++d) {          // MAX_ORDER - 1 hops
            if (cur != 0) {                    // START == 0
                const int st = state_start[cur];
                const int en = state_end[cur];
                const int idx = st + tid;      // lanes 0..15 cover A=16 arcs
                if (idx < en) {
                    const int lab = ilabels[idx];
                    if (!s_found[lab]) {       // labels unique within a state
                        s_score[lab] = acc + arcs_weights[idx];
                        s_next[lab]  = to_states[idx];
                        s_found[lab] = 1;
                    }
                }
                __syncwarp();                  // order depth d before d+1
                acc += backoff_weights[cur];
                cur  = backoff_to[cur];
            }
        }
        if (tid == 0) s_acc = acc;
    }
    __syncthreads();

    const float acc = s_acc;
    const size_t base = (size_t)b * (size_t)V;
    // Dense start-state fallback + overlay; fully coalesced streaming writes.
    for (int lab = tid; lab < V; lab += TPB) {
        float sc;
        int   nx;
        if (s_found[lab]) {
            sc = s_score[lab];
            nx = s_next[lab];
        } else {
            sc = acc + __ldg(&arcs_weights[lab]);   // start state: arc idx == label
            nx = __ldg(&to_states[lab]);
        }
        out_scores[base + lab] = sc;
        out_next[base + lab]   = (float)nx;         // exact: values < 2^24
    }
}

extern "C" void kernel_launch(void* const* d_in, const int* in_sizes, int n_in,
                              void* d_out, int out_size)
{
    // Classify inputs by element count — robust to dict-order vs
    // signature-order metadata (relative order within each size group is
    // identical in both).
    //   arcs group (largest size):  arcs_weights, ilabels, to_states
    //   state group (middle size):  backoff_weights, backoff_to, start, end
    //   states: the remaining (batch-sized) array
    long long max_sz = 0;
    for (int i = 0; i < n_in; ++i)
        if ((long long)in_sizes[i] > max_sz) max_sz = in_sizes[i];

    // state-group size = most common size that is neither max nor batch.
    // Identify batch array: with 8 inputs, sizes are {arcs x3, N x4, B x1}.
    // N appears 4 times; arcs 3 times; B once (and B != N != arcs).
    long long arc_sz = max_sz;
    long long n_sz = -1;
    // find the size occurring 4 times
    for (int i = 0; i < n_in; ++i) {
        int cnt = 0;
        for (int j = 0; j < n_in; ++j)
            if (in_sizes[j] == in_sizes[i]) ++cnt;
        if (cnt == 4) { n_sz = in_sizes[i]; break; }
    }

    const void* arc_grp[3];  int na = 0;
    const void* st_grp[4];   int ns = 0;
    const void* states_ptr = nullptr;
    long long B = 0;
    for (int i = 0; i < n_in; ++i) {
        if (in_sizes[i] == arc_sz && na < 3)      arc_grp[na++] = d_in[i];
        else if (in_sizes[i] == n_sz && ns < 4)   st_grp[ns++]  = d_in[i];
        else { states_ptr = d_in[i]; B = in_sizes[i]; }
    }

    const float* arcs_weights    = (const float*)arc_grp[0];
    const int*   ilabels         = (const int*)  arc_grp[1];
    const int*   to_states       = (const int*)  arc_grp[2];
    const float* backoff_weights = (const float*)st_grp[0];
    const int*   backoff_to      = (const int*)  st_grp[1];
    const int*   state_start     = (const int*)  st_grp[2];
    const int*   state_end       = (const int*)  st_grp[3];
    const int*   states          = (const int*)  states_ptr;

    const long long V = (long long)out_size / (2 * B);
    float* out_scores = (float*)d_out;
    float* out_next   = (float*)d_out + (size_t)B * (size_t)V;

    ngram_advance_kernel<<<(unsigned)B, TPB>>>(
        arcs_weights, backoff_weights, ilabels, to_states,
        backoff_to, state_start, state_end, states,
        out_scores, out_next, (int)V);
}

// round 2
// speedup vs baseline: 1.2827x; 1.2827x over previous
#include <cuda_runtime.h>
#include <cstddef>

// FastNGramLM advance, round 2: latency/issue-bound optimization.
//  - 128 threads/block -> 16 CTAs/SM -> 16 concurrent backoff chains per SM
//  - found-flag embedded in next (-1 = empty): one int2 shared table
//  - 4 labels/thread, float4/int4 vector loads + STG.128 stores
//  - dense fallback (start-state arcs) loaded BEFORE the barrier to overlap
//    the warp-0 pointer-chase latency
//
// Output layout: d_out[0 .. B*V)     = scores (float32)
//                d_out[B*V .. 2*B*V) = next_states (exact float32, < 2^24)

#define TPB  128
#define VMAX 1024

__global__ __launch_bounds__(TPB)
void ngram_advance_kernel(const float*  __restrict__ arcs_weights,
                          const float*  __restrict__ backoff_weights,
                          const int*    __restrict__ ilabels,
                          const int*    __restrict__ to_states,
                          const int*    __restrict__ backoff_to,
                          const int*    __restrict__ state_start,
                          const int*    __restrict__ state_end,
                          const int*    __restrict__ states,
                          float*        __restrict__ out_scores,
                          float*        __restrict__ out_next,
                          int V)
{
    // s_tab[lab].x = score bits, s_tab[lab].y = next state (-1 = empty)
    __shared__ int2  s_tab[VMAX];
    __shared__ float s_acc;

    const int b   = blockIdx.x;
    const int tid = threadIdx.x;

    // Clear the 'next' fields (found flag). 8 scalar STS per thread.
    #pragma unroll
    for (int i = tid; i < VMAX; i += TPB) s_tab[i].y = -1;

    // ---- Hoist dense-fallback loads (independent of the chain) ----
    // Each thread owns labels [tid*4, tid*4+3] and [tid*4+512, ...].
    float4 w0  = __ldg((const float4*)(arcs_weights + tid * 4));
    float4 w1  = __ldg((const float4*)(arcs_weights + tid * 4 + 512));
    int4   n0  = __ldg((const int4*)  (to_states    + tid * 4));
    int4   n1  = __ldg((const int4*)  (to_states    + tid * 4 + 512));

    __syncthreads();   // clear visible before chain scatters

    // ---- Warp 0: backoff chain (uniform branches; lanes 0..15 = arcs) ----
    if (tid < 32) {
        int   cur = __ldg(&states[b]);
        float acc = 0.0f;
        #pragma unroll
        for (int d = 0; d < 3; ++d) {          // MAX_ORDER - 1 hops
            if (cur != 0) {                    // START == 0
                const int st  = __ldg(&state_start[cur]);
                const int en  = __ldg(&state_end[cur]);
                const int idx = st + tid;
                if (idx < en) {
                    const int lab = __ldg(&ilabels[idx]);
                    if (s_tab[lab].y < 0) {    // first depth wins
                        int2 e;
                        e.x = __float_as_int(acc + __ldg(&arcs_weights[idx]));
                        e.y = __ldg(&to_states[idx]);
                        s_tab[lab] = e;
                    }
                }
                __syncwarp();                  // order depth d before d+1
                acc += __ldg(&backoff_weights[cur]);
                cur  = __ldg(&backoff_to[cur]);
            }
        }
        if (tid == 0) s_acc = acc;
    }
    __syncthreads();

    const float  acc  = s_acc;
    const size_t base = (size_t)b * (size_t)V;

    // ---- Streaming output: 2 groups of 4 consecutive labels per thread ----
    #pragma unroll
    for (int g = 0; g < 2; ++g) {
        const int lab0 = tid * 4 + g * 512;
        // two LDS.128: entries for labels lab0..lab0+3
        int4 ta = *(const int4*)&s_tab[lab0];       // labels lab0, lab0+1
        int4 tb = *(const int4*)&s_tab[lab0 + 2];   // labels lab0+2, lab0+3

        const float4 wf = g ? w1 : w0;
        const int4   nf = g ? n1 : n0;

        float4 sc, nx;
        sc.x = (ta.y >= 0) ? __int_as_float(ta.x) : acc + wf.x;
        sc.y = (ta.w >= 0) ? __int_as_float(ta.z) : acc + wf.y;
        sc.z = (tb.y >= 0) ? __int_as_float(tb.x) : acc + wf.z;
        sc.w = (tb.w >= 0) ? __int_as_float(tb.z) : acc + wf.w;

        nx.x = (float)((ta.y >= 0) ? ta.y : nf.x);
        nx.y = (float)((ta.w >= 0) ? ta.w : nf.y);
        nx.z = (float)((tb.y >= 0) ? tb.y : nf.z);
        nx.w = (float)((tb.w >= 0) ? tb.w : nf.w);

        *(float4*)&out_scores[base + lab0] = sc;
        *(float4*)&out_next  [base + lab0] = nx;
    }
}

extern "C" void kernel_launch(void* const* d_in, const int* in_sizes, int n_in,
                              void* d_out, int out_size)
{
    // Classify inputs by element count (robust to metadata ordering):
    //   arcs group (3x largest):  arcs_weights, ilabels, to_states
    //   state group (4x middle):  backoff_weights, backoff_to, start, end
    //   states: the remaining batch-sized array
    long long max_sz = 0;
    for (int i = 0; i < n_in; ++i)
        if ((long long)in_sizes[i] > max_sz) max_sz = in_sizes[i];

    long long arc_sz = max_sz;
    long long n_sz = -1;
    for (int i = 0; i < n_in; ++i) {
        int cnt = 0;
        for (int j = 0; j < n_in; ++j)
            if (in_sizes[j] == in_sizes[i]) ++cnt;
        if (cnt == 4) { n_sz = in_sizes[i]; break; }
    }

    const void* arc_grp[3];  int na = 0;
    const void* st_grp[4];   int ns = 0;
    const void* states_ptr = nullptr;
    long long B = 0;
    for (int i = 0; i < n_in; ++i) {
        if (in_sizes[i] == arc_sz && na < 3)      arc_grp[na++] = d_in[i];
        else if (in_sizes[i] == n_sz && ns < 4)   st_grp[ns++]  = d_in[i];
        else { states_ptr = d_in[i]; B = in_sizes[i]; }
    }

    const float* arcs_weights    = (const float*)arc_grp[0];
    const int*   ilabels         = (const int*)  arc_grp[1];
    const int*   to_states       = (const int*)  arc_grp[2];
    const float* backoff_weights = (const float*)st_grp[0];
    const int*   backoff_to      = (const int*)  st_grp[1];
    const int*   state_start     = (const int*)  st_grp[2];
    const int*   state_end       = (const int*)  st_grp[3];
    const int*   states          = (const int*)  states_ptr;

    const long long V = (long long)out_size / (2 * B);
    float* out_scores = (float*)d_out;
    float* out_next   = (float*)d_out + (size_t)B * (size_t)V;

    ngram_advance_kernel<<<(unsigned)B, TPB>>>(
        arcs_weights, backoff_weights, ilabels, to_states,
        backoff_to, state_start, state_end, states,
        out_scores, out_next, (int)V);
}

// round 3
// speedup vs baseline: 1.3073x; 1.0192x over previous
#include <cuda_runtime.h>
#include <cstddef>

// FastNGramLM advance, round 3: split the serial backoff chain (latency-bound,
// tiny) from the dense streaming write (throughput-bound, big).
//
// Kernel A: 16 lanes per hypothesis chase the 3-hop backoff chain and emit a
//           compact record: 48 ordered overlay entries + accumulated backoff.
//           All 8192 chains run fully in parallel -> latency overlapped.
// Kernel B: one block per hypothesis. No dependent pointer-chase: load the
//           compact record (one coalesced L2 round), scatter 3 ordered passes
//           into the smem table, stream vectorized output.
//
// Output layout: d_out[0 .. B*V)     = scores (float32)
//                d_out[B*V .. 2*B*V) = next_states (exact float32, < 2^24)

#define BMAX  8192
#define VMAX  1024
#define DEPTH 3          // MAX_ORDER - 1
#define ARCS  16         // arcs per non-start state
#define OVN   (DEPTH * ARCS)   // 48 overlay entries per hypothesis

// Scratch (no cudaMalloc allowed): ~4.7 MB
__device__ int   g_ov_lab[BMAX * OVN];
__device__ float g_ov_scr[BMAX * OVN];
__device__ int   g_ov_nxt[BMAX * OVN];
__device__ float g_acc   [BMAX];

// ---------------- Kernel A: backoff chains ----------------
__global__ __launch_bounds__(256)
void chain_kernel(const float* __restrict__ arcs_weights,
                  const float* __restrict__ backoff_weights,
                  const int*   __restrict__ ilabels,
                  const int*   __restrict__ to_states,
                  const int*   __restrict__ backoff_to,
                  const int*   __restrict__ state_start,
                  const int*   __restrict__ state_end,
                  const int*   __restrict__ states,
                  int B)
{
    const int t    = blockIdx.x * blockDim.x + threadIdx.x;
    const int h    = t >> 4;
    const int lane = t & 15;
    if (h >= B) return;

    int   cur = states[h];
    float acc = 0.0f;

    #pragma unroll
    for (int d = 0; d < DEPTH; ++d) {
        int   lab = -1;
        float sc  = 0.0f;
        int   nx  = 0;
        if (cur != 0) {                        // START == 0
            const int st  = state_start[cur];
            const int en  = state_end[cur];
            const int idx = st + lane;
            if (idx < en) {
                lab = ilabels[idx];
                sc  = acc + arcs_weights[idx];
                nx  = to_states[idx];
            }
            acc += backoff_weights[cur];
            cur  = backoff_to[cur];
        }
        const int o = h * OVN + d * ARCS + lane;
        g_ov_lab[o] = lab;
        g_ov_scr[o] = sc;
        g_ov_nxt[o] = nx;
    }
    if (lane == 0) g_acc[h] = acc;
}

// ---------------- Kernel B: streaming write ----------------
#define TPB 128

__global__ __launch_bounds__(TPB)
void write_kernel(const float* __restrict__ arcs_weights,
                  const int*   __restrict__ to_states,
                  float*       __restrict__ out_scores,
                  float*       __restrict__ out_next,
                  int V)
{
    // s_tab[lab].x = score bits, s_tab[lab].y = next (-1 = empty)
    __shared__ int2 s_tab[VMAX];

    const int h   = blockIdx.x;
    const int tid = threadIdx.x;

    // clear found flags
    #pragma unroll
    for (int i = tid; i < VMAX; i += TPB) s_tab[i].y = -1;

    // ---- prefetch dense fallback (independent) ----
    float4 w0 = __ldg((const float4*)(arcs_weights + tid * 4));
    float4 w1 = __ldg((const float4*)(arcs_weights + tid * 4 + 512));
    int4   n0 = __ldg((const int4*)  (to_states    + tid * 4));
    int4   n1 = __ldg((const int4*)  (to_states    + tid * 4 + 512));
    const float acc = g_acc[h];                 // broadcast load (L2)

    // ---- prefetch overlay record (lanes 0..15, all depths, MLP=3) ----
    int   lab[DEPTH];
    float scr[DEPTH];
    int   nxt[DEPTH];
    if (tid < ARCS) {
        #pragma unroll
        for (int d = 0; d < DEPTH; ++d) {
            const int o = h * OVN + d * ARCS + tid;
            lab[d] = g_ov_lab[o];
            scr[d] = g_ov_scr[o];
            nxt[d] = g_ov_nxt[o];
        }
    }
    __syncthreads();   // clear visible

    // ---- ordered scatter: depth d wins over depth d+1 ----
    if (tid < ARCS) {
        #pragma unroll
        for (int d = 0; d < DEPTH; ++d) {
            if (lab[d] >= 0 && s_tab[lab[d]].y < 0) {
                int2 e;
                e.x = __float_as_int(scr[d]);
                e.y = nxt[d];
                s_tab[lab[d]] = e;
            }
            __syncwarp(0x0000FFFFu);
        }
    }
    __syncthreads();

    const size_t base = (size_t)h * (size_t)V;

    // ---- streaming output: 2 groups of 4 consecutive labels per thread ----
    #pragma unroll
    for (int g = 0; g < 2; ++g) {
        const int lab0 = tid * 4 + g * 512;
        int4 ta = *(const int4*)&s_tab[lab0];       // labels lab0, lab0+1
        int4 tb = *(const int4*)&s_tab[lab0 + 2];   // labels lab0+2, lab0+3

        const float4 wf = g ? w1 : w0;
        const int4   nf = g ? n1 : n0;

        float4 sc, nx;
        sc.x = (ta.y >= 0) ? __int_as_float(ta.x) : acc + wf.x;
        sc.y = (ta.w >= 0) ? __int_as_float(ta.z) : acc + wf.y;
        sc.z = (tb.y >= 0) ? __int_as_float(tb.x) : acc + wf.z;
        sc.w = (tb.w >= 0) ? __int_as_float(tb.z) : acc + wf.w;

        nx.x = (float)((ta.y >= 0) ? ta.y : nf.x);
        nx.y = (float)((ta.w >= 0) ? ta.w : nf.y);
        nx.z = (float)((tb.y >= 0) ? tb.y : nf.z);
        nx.w = (float)((tb.w >= 0) ? tb.w : nf.w);

        *(float4*)&out_scores[base + lab0] = sc;
        *(float4*)&out_next  [base + lab0] = nx;
    }
}

extern "C" void kernel_launch(void* const* d_in, const int* in_sizes, int n_in,
                              void* d_out, int out_size)
{
    // Classify inputs by element count (robust to metadata ordering):
    //   arcs group (3x largest):  arcs_weights, ilabels, to_states
    //   state group (4x middle):  backoff_weights, backoff_to, start, end
    //   states: the remaining batch-sized array
    long long max_sz = 0;
    for (int i = 0; i < n_in; ++i)
        if ((long long)in_sizes[i] > max_sz) max_sz = in_sizes[i];

    long long arc_sz = max_sz;
    long long n_sz = -1;
    for (int i = 0; i < n_in; ++i) {
        int cnt = 0;
        for (int j = 0; j < n_in; ++j)
            if (in_sizes[j] == in_sizes[i]) ++cnt;
        if (cnt == 4) { n_sz = in_sizes[i]; break; }
    }

    const void* arc_grp[3];  int na = 0;
    const void* st_grp[4];   int ns = 0;
    const void* states_ptr = nullptr;
    long long B = 0;
    for (int i = 0; i < n_in; ++i) {
        if (in_sizes[i] == arc_sz && na < 3)      arc_grp[na++] = d_in[i];
        else if (in_sizes[i] == n_sz && ns < 4)   st_grp[ns++]  = d_in[i];
        else { states_ptr = d_in[i]; B = in_sizes[i]; }
    }

    const float* arcs_weights    = (const float*)arc_grp[0];
    const int*   ilabels         = (const int*)  arc_grp[1];
    const int*   to_states       = (const int*)  arc_grp[2];
    const float* backoff_weights = (const float*)st_grp[0];
    const int*   backoff_to      = (const int*)  st_grp[1];
    const int*   state_start     = (const int*)  st_grp[2];
    const int*   state_end       = (const int*)  st_grp[3];
    const int*   states          = (const int*)  states_ptr;

    const long long V = (long long)out_size / (2 * B);
    float* out_scores = (float*)d_out;
    float* out_next   = (float*)d_out + (size_t)B * (size_t)V;

    const int chainThreads = 256;
    const int chainGrid = (int)((B * ARCS + chainThreads - 1) / chainThreads);
    chain_kernel<<<chainGrid, chainThreads>>>(
        arcs_weights, backoff_weights, ilabels, to_states,
        backoff_to, state_start, state_end, states, (int)B);

    write_kernel<<<(unsigned)B, TPB>>>(
        arcs_weights, to_states, out_scores, out_next, (int)V);
}

// round 4
// speedup vs baseline: 1.4273x; 1.0917x over previous
#include <cuda_runtime.h>
#include <cstddef>

// FastNGramLM advance, round 4.
// Kernel A (chain): 16 lanes/hyp chase backoff chain, emit packed int4 record
//                   {lab, score_bits, next, pad} x 48 + acc.
// Kernel B (write): 8 hypotheses per 128-thread block, grid=1024 (single
//                   resident wave). Full table clear ONCE per block, then
//                   reset only touched entries per hypothesis. Next
//                   hypothesis's overlay prefetched during current output.
//
// Output: d_out[0..B*V) = scores f32, d_out[B*V..2BV) = next as exact f32.

#define BMAX  8192
#define VMAX  1024
#define DEPTH 3
#define ARCS  16
#define HPB   8          // hypotheses per write-block
#define TPB   128

// packed overlay: [(h*DEPTH + d)*ARCS + lane] = {lab, score_bits, next, pad}
__device__ int4  g_ov [BMAX * DEPTH * ARCS];
__device__ float g_acc[BMAX];

// ---------------- Kernel A: backoff chains ----------------
__global__ __launch_bounds__(256)
void chain_kernel(const float* __restrict__ arcs_weights,
                  const float* __restrict__ backoff_weights,
                  const int*   __restrict__ ilabels,
                  const int*   __restrict__ to_states,
                  const int*   __restrict__ backoff_to,
                  const int*   __restrict__ state_start,
                  const int*   __restrict__ state_end,
                  const int*   __restrict__ states,
                  int B)
{
    const int t    = blockIdx.x * blockDim.x + threadIdx.x;
    const int h    = t >> 4;
    const int lane = t & 15;
    if (h >= B) return;

    int   cur = states[h];
    float acc = 0.0f;

    #pragma unroll
    for (int d = 0; d < DEPTH; ++d) {
        int4 rec = make_int4(-1, 0, 0, 0);
        if (cur != 0) {                       // START == 0
            const int st  = state_start[cur];
            const int en  = state_end[cur];
            const int idx = st + lane;
            if (idx < en) {
                rec.x = ilabels[idx];
                rec.y = __float_as_int(acc + arcs_weights[idx]);
                rec.z = to_states[idx];
            }
            acc += backoff_weights[cur];
            cur  = backoff_to[cur];
        }
        g_ov[(h * DEPTH + d) * ARCS + lane] = rec;
    }
    if (lane == 0) g_acc[h] = acc;
}

// ---------------- Kernel B: streaming write ----------------
__global__ __launch_bounds__(TPB)
void write_kernel(const float* __restrict__ arcs_weights,
                  const int*   __restrict__ to_states,
                  float*       __restrict__ out_scores,
                  float*       __restrict__ out_next,
                  int B, int V)
{
    __shared__ int2  s_tab[VMAX];   // .x = score bits, .y = next (-1 empty)
    __shared__ float s_acc[HPB];

    const int tid = threadIdx.x;
    const int h0  = blockIdx.x * HPB;

    // full clear once per block
    #pragma unroll
    for (int i = tid; i < VMAX; i += TPB) s_tab[i].y = -1;

    // dense fallback, loaded once per block, held in registers
    const float4 w0 = __ldg((const float4*)(arcs_weights + tid * 4));
    const float4 w1 = __ldg((const float4*)(arcs_weights + tid * 4 + 512));
    const int4   n0 = __ldg((const int4*)  (to_states    + tid * 4));
    const int4   n1 = __ldg((const int4*)  (to_states    + tid * 4 + 512));

    if (tid < HPB && h0 + tid < B) s_acc[tid] = g_acc[h0 + tid];

    // prefetch overlay for first hypothesis
    int4 ov[DEPTH];
    if (tid < ARCS) {
        #pragma unroll
        for (int d = 0; d < DEPTH; ++d)
            ov[d] = g_ov[(h0 * DEPTH + d) * ARCS + tid];
    }
    __syncthreads();

    for (int j = 0; j < HPB; ++j) {
        const int h = h0 + j;
        if (h >= B) break;

        // ---- scatter (depth order = precedence) ----
        if (tid < ARCS) {
            #pragma unroll
            for (int d = 0; d < DEPTH; ++d) {
                if (ov[d].x >= 0 && s_tab[ov[d].x].y < 0)
                    s_tab[ov[d].x] = make_int2(ov[d].y, ov[d].z);
                __syncwarp(0x0000FFFFu);
            }
        }

        // ---- prefetch next hypothesis's overlay (hidden under output) ----
        int4 ovn[DEPTH];
        if (tid < ARCS && j + 1 < HPB && h + 1 < B) {
            #pragma unroll
            for (int d = 0; d < DEPTH; ++d)
                ovn[d] = g_ov[((h + 1) * DEPTH + d) * ARCS + tid];
        }
        __syncthreads();   // scatter visible to readers

        const float  acc  = s_acc[j];
        const size_t base = (size_t)h * (size_t)V;

        #pragma unroll
        for (int g = 0; g < 2; ++g) {
            const int lab0 = tid * 4 + g * 512;
            int4 ta = *(const int4*)&s_tab[lab0];
            int4 tb = *(const int4*)&s_tab[lab0 + 2];

            const float4 wf = g ? w1 : w0;
            const int4   nf = g ? n1 : n0;

            float4 sc, nx;
            sc.x = (ta.y >= 0) ? __int_as_float(ta.x) : acc + wf.x;
            sc.y = (ta.w >= 0) ? __int_as_float(ta.z) : acc + wf.y;
            sc.z = (tb.y >= 0) ? __int_as_float(tb.x) : acc + wf.z;
            sc.w = (tb.w >= 0) ? __int_as_float(tb.z) : acc + wf.w;

            nx.x = (float)((ta.y >= 0) ? ta.y : nf.x);
            nx.y = (float)((ta.w >= 0) ? ta.w : nf.y);
            nx.z = (float)((tb.y >= 0) ? tb.y : nf.z);
            nx.w = (float)((tb.w >= 0) ? tb.w : nf.w);

            *(float4*)&out_scores[base + lab0] = sc;
            *(float4*)&out_next  [base + lab0] = nx;
        }
        __syncthreads();   // readers done before reset

        // ---- reset only touched entries ----
        if (tid < ARCS) {
            #pragma unroll
            for (int d = 0; d < DEPTH; ++d) {
                if (ov[d].x >= 0) s_tab[ov[d].x].y = -1;
                ov[d] = ovn[d];
            }
        }
        __syncthreads();   // reset visible before next scatter
    }
}

extern "C" void kernel_launch(void* const* d_in, const int* in_sizes, int n_in,
                              void* d_out, int out_size)
{
    // Classify inputs by element count (robust to metadata ordering):
    //   arcs group (3x largest):  arcs_weights, ilabels, to_states
    //   state group (4x middle):  backoff_weights, backoff_to, start, end
    //   states: the remaining batch-sized array
    long long max_sz = 0;
    for (int i = 0; i < n_in; ++i)
        if ((long long)in_sizes[i] > max_sz) max_sz = in_sizes[i];

    long long arc_sz = max_sz;
    long long n_sz = -1;
    for (int i = 0; i < n_in; ++i) {
        int cnt = 0;
        for (int j = 0; j < n_in; ++j)
            if (in_sizes[j] == in_sizes[i]) ++cnt;
        if (cnt == 4) { n_sz = in_sizes[i]; break; }
    }

    const void* arc_grp[3];  int na = 0;
    const void* st_grp[4];   int ns = 0;
    const void* states_ptr = nullptr;
    long long B = 0;
    for (int i = 0; i < n_in; ++i) {
        if (in_sizes[i] == arc_sz && na < 3)      arc_grp[na++] = d_in[i];
        else if (in_sizes[i] == n_sz && ns < 4)   st_grp[ns++]  = d_in[i];
        else { states_ptr = d_in[i]; B = in_sizes[i]; }
    }

    const float* arcs_weights    = (const float*)arc_grp[0];
    const int*   ilabels         = (const int*)  arc_grp[1];
    const int*   to_states       = (const int*)  arc_grp[2];
    const float* backoff_weights = (const float*)st_grp[0];
    const int*   backoff_to      = (const int*)  st_grp[1];
    const int*   state_start     = (const int*)  st_grp[2];
    const int*   state_end       = (const int*)  st_grp[3];
    const int*   states          = (const int*)  states_ptr;

    const long long V = (long long)out_size / (2 * B);
    float* out_scores = (float*)d_out;
    float* out_next   = (float*)d_out + (size_t)B * (size_t)V;

    const int chainThreads = 256;
    const int chainGrid = (int)((B * ARCS + chainThreads - 1) / chainThreads);
    chain_kernel<<<chainGrid, chainThreads>>>(
        arcs_weights, backoff_weights, ilabels, to_states,
        backoff_to, state_start, state_end, states, (int)B);

    const int writeGrid = (int)((B + HPB - 1) / HPB);
    write_kernel<<<writeGrid, TPB>>>(
        arcs_weights, to_states, out_scores, out_next, (int)B, (int)V);
}

// round 5
// speedup vs baseline: 1.5295x; 1.0716x over previous
#include <cuda_runtime.h>
#include <cstddef>

// FastNGramLM advance, round 5: single fused kernel.
//  - 256 threads/block, 8 hypotheses/block, grid = B/8 = 1024 (single wave)
//  - chain phase: threads 0..127 = 8 chains x 16 lanes, results to smem
//    (overlaps with independent dense-fallback loads)
//  - dense fallback cached in smem (regs stay low -> 7 blocks/SM)
//  - 2 block barriers per hypothesis (scatter+reset both by warp 0)
//
// Output: d_out[0..B*V) = scores f32, d_out[B*V..2BV) = next as exact f32.

#define VMAX  1024
#define DEPTH 3
#define ARCS  16
#define HPB   8
#define TPB   256

__global__ __launch_bounds__(TPB, 7)
void ngram_fused_kernel(const float* __restrict__ arcs_weights,
                        const float* __restrict__ backoff_weights,
                        const int*   __restrict__ ilabels,
                        const int*   __restrict__ to_states,
                        const int*   __restrict__ backoff_to,
                        const int*   __restrict__ state_start,
                        const int*   __restrict__ state_end,
                        const int*   __restrict__ states,
                        float*       __restrict__ out_scores,
                        float*       __restrict__ out_next,
                        int B, int V)
{
    __shared__ int2  s_tab[VMAX];               // .x score bits, .y next (-1 empty)
    __shared__ float s_wf [VMAX];               // dense fallback weights
    __shared__ int   s_nf [VMAX];               // dense fallback next
    __shared__ int   s_lab[HPB][DEPTH][ARCS];
    __shared__ int   s_scr[HPB][DEPTH][ARCS];
    __shared__ int   s_nxt[HPB][DEPTH][ARCS];
    __shared__ float s_acc[HPB];

    const int tid = threadIdx.x;
    const int h0  = blockIdx.x * HPB;

    // ---- dense fallback -> smem, clear table (vectorized) ----
    {
        const float4 w = __ldg((const float4*)arcs_weights + tid);
        const int4   n = __ldg((const int4*)  to_states    + tid);
        *(float4*)&s_wf[tid * 4] = w;
        *(int4*)  &s_nf[tid * 4] = n;
        const int4 empty2 = make_int4(0, -1, 0, -1);   // two int2 with .y=-1
        *(int4*)&s_tab[tid * 4]     = empty2;
        *(int4*)&s_tab[tid * 4 + 2] = empty2;
    }

    // ---- chain phase: 8 hyps x 16 lanes (threads 0..127) ----
    if (tid < HPB * ARCS) {
        const int j    = tid >> 4;
        const int lane = tid & 15;
        const int h    = h0 + j;
        int   cur = (h < B) ? __ldg(&states[h]) : 0;
        float acc = 0.0f;
        #pragma unroll
        for (int d = 0; d < DEPTH; ++d) {
            int lab = -1, scb = 0, nx = 0;
            if (cur != 0) {                    // START == 0
                const int st  = __ldg(&state_start[cur]);
                const int en  = __ldg(&state_end[cur]);
                const int idx = st + lane;
                if (idx < en) {
                    lab = __ldg(&ilabels[idx]);
                    scb = __float_as_int(acc + __ldg(&arcs_weights[idx]));
                    nx  = __ldg(&to_states[idx]);
                }
                acc += __ldg(&backoff_weights[cur]);
                cur  = __ldg(&backoff_to[cur]);
            }
            s_lab[j][d][lane] = lab;
            s_scr[j][d][lane] = scb;
            s_nxt[j][d][lane] = nx;
        }
        if (lane == 0) s_acc[j] = acc;
    }
    __syncthreads();

    // ---- per-hypothesis: scatter -> output -> reset ----
    for (int j = 0; j < HPB; ++j) {
        const int h = h0 + j;
        if (h >= B) break;

        // scatter with depth precedence (warp 0, lanes 0..15)
        if (tid < 32) {
            #pragma unroll
            for (int d = 0; d < DEPTH; ++d) {
                if (tid < ARCS) {
                    const int lab = s_lab[j][d][tid];
                    if (lab >= 0 && s_tab[lab].y < 0)
                        s_tab[lab] = make_int2(s_scr[j][d][tid],
                                               s_nxt[j][d][tid]);
                }
                __syncwarp();
            }
        }
        __syncthreads();   // scatter visible to all readers

        const float  acc  = s_acc[j];
        const size_t base = (size_t)h * (size_t)V;
        const int    lab0 = tid * 4;

        const int4 ta = *(const int4*)&s_tab[lab0];       // labels lab0,+1
        const int4 tb = *(const int4*)&s_tab[lab0 + 2];   // labels +2,+3
        const float4 wf = *(const float4*)&s_wf[lab0];
        const int4   nf = *(const int4*)  &s_nf[lab0];

        float4 sc, nx;
        sc.x = (ta.y >= 0) ? __int_as_float(ta.x) : acc + wf.x;
        sc.y = (ta.w >= 0) ? __int_as_float(ta.z) : acc + wf.y;
        sc.z = (tb.y >= 0) ? __int_as_float(tb.x) : acc + wf.z;
        sc.w = (tb.w >= 0) ? __int_as_float(tb.z) : acc + wf.w;

        nx.x = (float)((ta.y >= 0) ? ta.y : nf.x);
        nx.y = (float)((ta.w >= 0) ? ta.w : nf.y);
        nx.z = (float)((tb.y >= 0) ? tb.y : nf.z);
        nx.w = (float)((tb.w >= 0) ? tb.w : nf.w);

        *(float4*)&out_scores[base + lab0] = sc;
        *(float4*)&out_next  [base + lab0] = nx;

        __syncthreads();   // all reads of s_tab done before reset

        // reset touched entries (warp 0; next scatter is same warp ->
        // program order, no extra block barrier needed)
        if (tid < ARCS) {
            #pragma unroll
            for (int d = 0; d < DEPTH; ++d) {
                const int lab = s_lab[j][d][tid];
                if (lab >= 0) s_tab[lab].y = -1;
            }
        }
    }
}

extern "C" void kernel_launch(void* const* d_in, const int* in_sizes, int n_in,
                              void* d_out, int out_size)
{
    // Classify inputs by element count (robust to metadata ordering):
    //   arcs group (3x largest):  arcs_weights, ilabels, to_states
    //   state group (4x middle):  backoff_weights, backoff_to, start, end
    //   states: the remaining batch-sized array
    long long max_sz = 0;
    for (int i = 0; i < n_in; ++i)
        if ((long long)in_sizes[i] > max_sz) max_sz = in_sizes[i];

    long long arc_sz = max_sz;
    long long n_sz = -1;
    for (int i = 0; i < n_in; ++i) {
        int cnt = 0;
        for (int j = 0; j < n_in; ++j)
            if (in_sizes[j] == in_sizes[i]) ++cnt;
        if (cnt == 4) { n_sz = in_sizes[i]; break; }
    }

    const void* arc_grp[3];  int na = 0;
    const void* st_grp[4];   int ns = 0;
    const void* states_ptr = nullptr;
    long long B = 0;
    for (int i = 0; i < n_in; ++i) {
        if (in_sizes[i] == arc_sz && na < 3)      arc_grp[na++] = d_in[i];
        else if (in_sizes[i] == n_sz && ns < 4)   st_grp[ns++]  = d_in[i];
        else { states_ptr = d_in[i]; B = in_sizes[i]; }
    }

    const float* arcs_weights    = (const float*)arc_grp[0];
    const int*   ilabels         = (const int*)  arc_grp[1];
    const int*   to_states       = (const int*)  arc_grp[2];
    const float* backoff_weights = (const float*)st_grp[0];
    const int*   backoff_to      = (const int*)  st_grp[1];
    const int*   state_start     = (const int*)  st_grp[2];
    const int*   state_end       = (const int*)  st_grp[3];
    const int*   states          = (const int*)  states_ptr;

    const long long V = (long long)out_size / (2 * B);
    float* out_scores = (float*)d_out;
    float* out_next   = (float*)d_out + (size_t)B * (size_t)V;

    const int grid = (int)((B + HPB - 1) / HPB);
    ngram_fused_kernel<<<grid, TPB>>>(
        arcs_weights, backoff_weights, ilabels, to_states,
        backoff_to, state_start, state_end, states,
        out_scores, out_next, (int)B, (int)V);
}

// round 7
// speedup vs baseline: 1.8584x; 1.2150x over previous
#include <cuda_runtime.h>
#include <cstddef>

// FastNGramLM advance, round 7: round-6 design with the __syncwarp divergence
// deadlock fixed (all syncwarps now at uniform full-warp scope).
//  - 256 threads/block, HPB=8 hyps/block, grid=1024 (single wave)
//  - chain phase: threads 0..127 = 8 chains x 16 lanes -> smem records
//    (score pre-accumulated, next pre-converted to float)
//  - two tables + byte epoch tags: no reset; scatter(j+1) by warp 0 overlaps
//    output(j) by all warps -> 1 block barrier per hypothesis
//  - reverse-depth unconditional scatter: no found-check loads/branches
//  - dense fallback held in registers (weights + next-as-float)
//
// Output: d_out[0..B*V) = scores f32, d_out[B*V..2BV) = next as exact f32.

#define VMAX  1024
#define DEPTH 3
#define ARCS  16
#define HPB   8
#define TPB   256

__global__ __launch_bounds__(TPB, 7)
void ngram_fused_kernel(const float* __restrict__ arcs_weights,
                        const float* __restrict__ backoff_weights,
                        const int*   __restrict__ ilabels,
                        const int*   __restrict__ to_states,
                        const int*   __restrict__ backoff_to,
                        const int*   __restrict__ state_start,
                        const int*   __restrict__ state_end,
                        const int*   __restrict__ states,
                        float*       __restrict__ out_scores,
                        float*       __restrict__ out_next,
                        int B, int V)
{
    __shared__ __align__(16) float2        s_tab[2][VMAX];  // {score, next_f}
    __shared__ __align__(4)  unsigned char s_tag[2][VMAX];  // epoch byte
    __shared__ int    s_lab[HPB][DEPTH][ARCS];
    __shared__ float2 s_ent[HPB][DEPTH][ARCS];
    __shared__ float  s_acc[HPB];

    const int tid = threadIdx.x;
    const int h0  = blockIdx.x * HPB;

    // ---- init tags (0xFF != any epoch 0..7) ----
    ((unsigned*)s_tag)[tid]       = 0xFFFFFFFFu;
    ((unsigned*)s_tag)[tid + 256] = 0xFFFFFFFFu;

    // ---- dense fallback -> registers (independent of chain) ----
    const float4 wf  = __ldg((const float4*)arcs_weights + tid);
    const int4   nfi = __ldg((const int4*)  to_states    + tid);
    float4 nfv;
    nfv.x = (float)nfi.x; nfv.y = (float)nfi.y;
    nfv.z = (float)nfi.z; nfv.w = (float)nfi.w;

    // ---- chain phase: 8 hyps x 16 lanes (threads 0..127) ----
    if (tid < HPB * ARCS) {
        const int j    = tid >> 4;
        const int lane = tid & 15;
        const int h    = h0 + j;
        int   cur = (h < B) ? __ldg(&states[h]) : 0;
        float acc = 0.0f;
        #pragma unroll
        for (int d = 0; d < DEPTH; ++d) {
            int    lab = -1;
            float2 ent = make_float2(0.0f, 0.0f);
            if (cur != 0) {                    // START == 0
                const int st  = __ldg(&state_start[cur]);
                const int en  = __ldg(&state_end[cur]);
                const int idx = st + lane;
                if (idx < en) {
                    lab   = __ldg(&ilabels[idx]);
                    ent.x = acc + __ldg(&arcs_weights[idx]);
                    ent.y = (float)__ldg(&to_states[idx]);
                }
                acc += __ldg(&backoff_weights[cur]);
                cur  = __ldg(&backoff_to[cur]);
            }
            s_lab[j][d][lane] = lab;
            s_ent[j][d][lane] = ent;
        }
        if (lane == 0) s_acc[j] = acc;
    }
    __syncthreads();

    // ---- prime: scatter hyp 0 into table 0 (whole warp 0; lanes 0..15 work) ----
    if (tid < 32) {
        #pragma unroll
        for (int d = DEPTH - 1; d >= 0; --d) {  // reverse depth: shallow wins
            if (tid < ARCS) {
                const int lab = s_lab[0][d][tid];
                if (lab >= 0) {
                    s_tab[0][lab] = s_ent[0][d][tid];
                    s_tag[0][lab] = 0;
                }
            }
            __syncwarp();                        // full-warp scope: safe
        }
    }
    __syncthreads();

    // ---- main loop: output(j) from table p; warp0 scatters j+1 into !p ----
    for (int j = 0; j < HPB; ++j) {
        const int p = j & 1;

        // (j+1 < HPB) is uniform across warp 0 -> whole warp enters together
        if (tid < 32 && j + 1 < HPB) {
            const int q = p ^ 1;
            #pragma unroll
            for (int d = DEPTH - 1; d >= 0; --d) {
                if (tid < ARCS) {
                    const int lab = s_lab[j + 1][d][tid];
                    if (lab >= 0) {
                        s_tab[q][lab] = s_ent[j + 1][d][tid];
                        s_tag[q][lab] = (unsigned char)(j + 1);
                    }
                }
                __syncwarp();                    // full-warp scope: safe
            }
        }

        const int h = h0 + j;
        if (h < B) {
            const float  acc  = s_acc[j];
            const int    lab0 = tid * 4;
            const size_t base = (size_t)h * (size_t)V;

            const float4 e01 = *(const float4*)&s_tab[p][lab0];     // {s0,n0,s1,n1}
            const float4 e23 = *(const float4*)&s_tab[p][lab0 + 2]; // {s2,n2,s3,n3}
            const unsigned tags = *(const unsigned*)&s_tag[p][lab0];

            const unsigned jj = (unsigned)j;
            const bool v0 = ( tags        & 0xFFu) == jj;
            const bool v1 = ((tags >>  8) & 0xFFu) == jj;
            const bool v2 = ((tags >> 16) & 0xFFu) == jj;
            const bool v3 = ((tags >> 24) & 0xFFu) == jj;

            float4 sc, nx;
            sc.x = v0 ? e01.x : acc + wf.x;
            sc.y = v1 ? e01.z : acc + wf.y;
            sc.z = v2 ? e23.x : acc + wf.z;
            sc.w = v3 ? e23.z : acc + wf.w;
            nx.x = v0 ? e01.y : nfv.x;
            nx.y = v1 ? e01.w : nfv.y;
            nx.z = v2 ? e23.y : nfv.z;
            nx.w = v3 ? e23.w : nfv.w;

            *(float4*)&out_scores[base + lab0] = sc;
            *(float4*)&out_next  [base + lab0] = nx;
        }
        __syncthreads();   // output(j) reads done; table !p (scatter j+1) ready
    }
}

extern "C" void kernel_launch(void* const* d_in, const int* in_sizes, int n_in,
                              void* d_out, int out_size)
{
    // Classify inputs by element count (robust to metadata ordering):
    //   arcs group (3x largest):  arcs_weights, ilabels, to_states
    //   state group (4x middle):  backoff_weights, backoff_to, start, end
    //   states: the remaining batch-sized array
    long long max_sz = 0;
    for (int i = 0; i < n_in; ++i)
        if ((long long)in_sizes[i] > max_sz) max_sz = in_sizes[i];

    long long arc_sz = max_sz;
    long long n_sz = -1;
    for (int i = 0; i < n_in; ++i) {
        int cnt = 0;
        for (int j = 0; j < n_in; ++j)
            if (in_sizes[j] == in_sizes[i]) ++cnt;
        if (cnt == 4) { n_sz = in_sizes[i]; break; }
    }

    const void* arc_grp[3];  int na = 0;
    const void* st_grp[4];   int ns = 0;
    const void* states_ptr = nullptr;
    long long B = 0;
    for (int i = 0; i < n_in; ++i) {
        if (in_sizes[i] == arc_sz && na < 3)      arc_grp[na++] = d_in[i];
        else if (in_sizes[i] == n_sz && ns < 4)   st_grp[ns++]  = d_in[i];
        else { states_ptr = d_in[i]; B = in_sizes[i]; }
    }

    const float* arcs_weights    = (const float*)arc_grp[0];
    const int*   ilabels         = (const int*)  arc_grp[1];
    const int*   to_states       = (const int*)  arc_grp[2];
    const float* backoff_weights = (const float*)st_grp[0];
    const int*   backoff_to      = (const int*)  st_grp[1];
    const int*   state_start     = (const int*)  st_grp[2];
    const int*   state_end       = (const int*)  st_grp[3];
    const int*   states          = (const int*)  states_ptr;

    const long long V = (long long)out_size / (2 * B);
    float* out_scores = (float*)d_out;
    float* out_next   = (float*)d_out + (size_t)B * (size_t)V;

    const int grid = (int)((B + HPB - 1) / HPB);
    ngram_fused_kernel<<<grid, TPB>>>(
        arcs_weights, backoff_weights, ilabels, to_states,
        backoff_to, state_start, state_end, states,
        out_scores, out_next, (int)B, (int)V);
}